// round 7
// baseline (speedup 1.0000x reference)
#include <cuda_runtime.h>

#define B_    256
#define T_    4096
#define TWO_N 16
#define H_    64
#define P_    144
#define TBL   128
#define TPB   256
#define CHUNKS (T_/TPB)      // 16
#define NBLK  (B_*CHUNKS)    // 4096
#define SUPB  40             // supervised-loss blocks (40*1024 = 40960 elems)
#define ROWF  36             // floats per table row (144 B, 16B-aligned)
#define TROWS (TBL + 2)      // 129 data rows + 1 pad row (copy overrun safety)
#define CPY4  ((TBL + 1) * ROWF / 4)   // 1161 float4s to copy

// fp32 table, row i (stride 36 floats): 32 floats (lat_0,dlat_0,...,lat_15,dlat_15)
// at t=i/TBL, then 4 pad floats.  Flat for bulk copy.
__device__ __align__(16) float g_table[TROWS * ROWF];
__device__ float g_pd[NBLK];
__device__ float g_pp[NBLK];
__device__ float g_sup[SUPB];

// ---------------------------------------------------------------------------
// Kernel 1: tabulate latent/dlatent (4 entries per block, 64 threads each).
// Blocks 0..SUPB-1 also fold the supervised loss.
// ---------------------------------------------------------------------------
__global__ __launch_bounds__(256) void build_table(
    const float* __restrict__ W1, const float* __restrict__ b1,
    const float* __restrict__ W2, const float* __restrict__ b2,
    const float* __restrict__ pp, const float* __restrict__ pt,
    const float* __restrict__ icp, const float* __restrict__ ict) {

    __shared__ float s_th[4][64];
    __shared__ float s_dh[4][64];
    __shared__ float s_x[4][16], s_y[4][16];
    __shared__ float s_red[8];

    const int tid = threadIdx.x;
    const int el  = tid >> 6;
    const int j   = tid & 63;
    const int e   = blockIdx.x * 4 + el;

    if (e <= TBL) {
        float tv = (float)e / (float)TBL;
        float w1 = __ldg(W1 + j);
        float u  = fmaf(tv, w1, __ldg(b1 + j));
        float th = tanhf(u);
        s_th[el][j] = th;
        s_dh[el][j] = w1 * (1.f - th * th);
    }
    __syncthreads();

    {
        const int k = tid & 15;
        const int h = (tid >> 4) & 3;
        const int wi = (tid >> 5) & 1;
        float lat = 0.f, dlat = 0.f;
        if (e <= TBL) {
#pragma unroll
            for (int q = 0; q < 16; q++) {
                int jj = h * 16 + q;
                float w2 = __ldg(W2 + jj * 16 + k);
                lat  = fmaf(s_th[el][jj], w2, lat);
                dlat = fmaf(s_dh[el][jj], w2, dlat);
            }
        }
        lat  += __shfl_xor_sync(0xffffffffu, lat,  16);
        dlat += __shfl_xor_sync(0xffffffffu, dlat, 16);
        if (wi == 1 && (tid & 31) < 16) { s_x[el][k] = lat; s_y[el][k] = dlat; }
        __syncthreads();
        if (e <= TBL && wi == 0 && (tid & 31) < 16) {
            g_table[e * ROWF + 2 * k]     = lat + s_x[el][k] + __ldg(b2 + k);
            g_table[e * ROWF + 2 * k + 1] = dlat + s_y[el][k];
        }
    }

    if (blockIdx.x < SUPB) {
        const int ebase = blockIdx.x * 1024 + tid * 4;
        float4 a, t4;
        if (ebase < B_ * P_) {
            a  = __ldg((const float4*)(pp + ebase));
            t4 = __ldg((const float4*)(pt + ebase));
        } else {
            int r = ebase - B_ * P_;
            a  = __ldg((const float4*)(icp + r));
            t4 = __ldg((const float4*)(ict + r));
        }
        float dx = a.x - t4.x, dy = a.y - t4.y, dz = a.z - t4.z, dw = a.w - t4.w;
        float s = fmaf(dx, dx, fmaf(dy, dy, fmaf(dz, dz, dw * dw)));
#pragma unroll
        for (int o = 16; o; o >>= 1) s += __shfl_down_sync(0xffffffffu, s, o);
        if ((tid & 31) == 0) s_red[tid >> 5] = s;
        __syncthreads();
        if (tid == 0) {
            float tot = 0.f;
#pragma unroll
            for (int i = 0; i < 8; i++) tot += s_red[i];
            g_sup[blockIdx.x] = tot;
        }
    }
}

// ---------------------------------------------------------------------------
// Kernel 2: main loss. One block = (batch b, 256 t's). Table copied to smem
// once per block, then fully t-parallel: per-thread gather from smem, no
// staging, single __syncthreads after the copy.
// ---------------------------------------------------------------------------
__global__ __launch_bounds__(TPB) void main_kernel(
    const float* __restrict__ t_in,
    const float* __restrict__ x_target,
    const float* __restrict__ params) {

    __shared__ __align__(16) float s_tab[TROWS * ROWF];   // 18.6 KB
    __shared__ float s_par[P_];
    __shared__ float s_rd[TPB / 32], s_rp[TPB / 32];

    const int tid   = threadIdx.x;
    const int b     = blockIdx.x >> 4;
    const int chunk = blockIdx.x & (CHUNKS - 1);
    const int t0    = chunk * TPB;

    // bulk table copy (L2-resident source), 16B granules
    {
        const float4* src = (const float4*)g_table;
        float4* dst = (float4*)s_tab;
        for (int i = tid; i < CPY4; i += TPB) dst[i] = src[i];
    }
    if (tid < P_) s_par[tid] = __ldg(params + (size_t)b * P_ + tid);

    // own t, index+frac in registers
    float tv = __ldg(t_in + (size_t)b * T_ + t0 + tid);
    float p  = tv * (float)TBL;
    int   i  = (int)p;
    i = max(0, min(i, TBL - 1));
    float f = p - (float)i;
    __syncthreads();

    // ---- per-thread gather + lerp from smem table ----
    float lat[16], dlat[16];
    {
        const float4* lo4 = (const float4*)(s_tab + i * ROWF);
        const float4* hi4 = (const float4*)(s_tab + (i + 1) * ROWF);
#pragma unroll
        for (int c = 0; c < 8; c++) {
            float4 lo = lo4[c];
            float4 hi = hi4[c];
            lat[2 * c]      = fmaf(f, hi.x - lo.x, lo.x);
            dlat[2 * c]     = fmaf(f, hi.y - lo.y, lo.y);
            lat[2 * c + 1]  = fmaf(f, hi.z - lo.z, lo.z);
            dlat[2 * c + 1] = fmaf(f, hi.w - lo.w, lo.w);
        }
    }

    // observables in place: lat[8+k] <- relu(q-mu); dlat[8+k] <- jvp
#pragma unroll
    for (int k = 0; k < 8; k++) {
        float s = lat[8 + k] - s_par[8 + k];
        lat[8 + k]  = fmaxf(s, 0.f);
        dlat[8 + k] = (s > 0.f) ? dlat[8 + k] : 0.f;
    }

    float acc_p = 0.f;
#pragma unroll
    for (int k = 0; k < 8; k++) {
        float pix = 0.f, ga = 0.f;
#pragma unroll
        for (int j = 0; j < 8; j++) {
            pix = fmaf(s_par[16 + k * 8 + j], lat[8 + j], pix);
            ga  = fmaf(s_par[80 + k * 8 + j], lat[j],     ga);
        }
        float d1 = dlat[k] - (s_par[k] + pix - lat[k]);
        acc_p = fmaf(d1, d1, acc_p);
        float d2 = dlat[8 + k] - ga * (s_par[8 + k] - lat[8 + k]);
        acc_p = fmaf(d2, d2, acc_p);
    }

    // data loss: state == lat[0..15]; coalesced stride-T loads, 16-deep MLP
    float acc_d = 0.f;
    const float* xt = x_target + (size_t)b * TWO_N * T_ + t0 + tid;
#pragma unroll
    for (int k = 0; k < 16; k++) {
        float d = lat[k] - __ldg(xt + (size_t)k * T_);
        acc_d = fmaf(d, d, acc_d);
    }

    // ---- block reduction ----
#pragma unroll
    for (int o = 16; o; o >>= 1) {
        acc_d += __shfl_down_sync(0xffffffffu, acc_d, o);
        acc_p += __shfl_down_sync(0xffffffffu, acc_p, o);
    }
    const int lane = tid & 31, wid = tid >> 5;
    if (lane == 0) { s_rd[wid] = acc_d; s_rp[wid] = acc_p; }
    __syncthreads();
    if (tid == 0) {
        float sd = 0.f, sp = 0.f;
#pragma unroll
        for (int ii = 0; ii < TPB / 32; ii++) { sd += s_rd[ii]; sp += s_rp[ii]; }
        g_pd[blockIdx.x] = sd;
        g_pp[blockIdx.x] = sp;
    }
}

// ---------------------------------------------------------------------------
// Kernel 3: finalize — deterministic double sums of tiny partial arrays.
// ---------------------------------------------------------------------------
__global__ void finalize(float* __restrict__ out) {
    const int tid = threadIdx.x;
    double sd = 0.0, sp = 0.0;
    for (int i = tid; i < NBLK; i += 256) {
        sd += (double)g_pd[i];
        sp += (double)g_pp[i];
    }
    double ss = (tid < SUPB) ? (double)g_sup[tid] : 0.0;
    __shared__ double r1[256], r2[256], r3[256];
    r1[tid] = sd; r2[tid] = sp; r3[tid] = ss;
    __syncthreads();
    for (int o = 128; o; o >>= 1) {
        if (tid < o) { r1[tid] += r1[tid + o]; r2[tid] += r2[tid + o]; r3[tid] += r3[tid + o]; }
        __syncthreads();
    }
    if (tid == 0) {
        double res = (r1[0] + r2[0]) / 16777216.0 + r3[0] / 40960.0;
        out[0] = (float)res;
    }
}

// ---------------------------------------------------------------------------
extern "C" void kernel_launch(void* const* d_in, const int* in_sizes, int n_in,
                              void* d_out, int out_size) {
    const float* t   = (const float*)d_in[0];
    const float* xt  = (const float*)d_in[1];
    const float* pp  = (const float*)d_in[2];
    const float* pt  = (const float*)d_in[3];
    const float* icp = (const float*)d_in[4];
    const float* ict = (const float*)d_in[5];
    const float* W1  = (const float*)d_in[6];
    const float* b1  = (const float*)d_in[7];
    const float* W2  = (const float*)d_in[8];
    const float* b2  = (const float*)d_in[9];

    int tbl_blocks = (TBL + 1 + 3) / 4;            // 33
    int grid1 = tbl_blocks > SUPB ? tbl_blocks : SUPB;  // 40
    build_table<<<grid1, 256>>>(W1, b1, W2, b2, pp, pt, icp, ict);
    main_kernel<<<NBLK, TPB>>>(t, xt, pp);
    finalize<<<1, 256>>>((float*)d_out);
}

// round 8
// speedup vs baseline: 1.1289x; 1.1289x over previous
#include <cuda_runtime.h>

#define B_    256
#define T_    4096
#define TWO_N 16
#define H_    64
#define P_    144
#define TBL   128
#define TPB   256
#define CHUNKS (T_/TPB)      // 16
#define NBLK  (B_*CHUNKS)    // 4096
#define SUPB  40             // supervised-loss blocks (40*1024 = 40960 elems)
#define PAD   36             // stage row stride (floats): 4*tid mod 32 covers all banks

// fp32 table row i: 32 floats = (lat_0,dlat_0,...,lat_15,dlat_15) at t=i/TBL.
// (TBL+1)*128 B = 16.5 KB -> L1-resident.
__device__ float g_table[TBL + 1][32];
__device__ float g_pd[NBLK];
__device__ float g_pp[NBLK];
__device__ float g_sup[SUPB];

// ---------------------------------------------------------------------------
// Kernel 1: tabulate latent/dlatent. 4 entries per 256-thread block; 64
// threads per entry. Blocks 0..SUPB-1 also fold the supervised loss.
// ---------------------------------------------------------------------------
__global__ __launch_bounds__(256) void build_table(
    const float* __restrict__ W1, const float* __restrict__ b1,
    const float* __restrict__ W2, const float* __restrict__ b2,
    const float* __restrict__ pp, const float* __restrict__ pt,
    const float* __restrict__ icp, const float* __restrict__ ict) {

    __shared__ float s_th[4][64];
    __shared__ float s_dh[4][64];
    __shared__ float s_x[4][16], s_y[4][16];
    __shared__ float s_red[8];

    const int tid = threadIdx.x;
    const int el  = tid >> 6;
    const int j   = tid & 63;
    const int e   = blockIdx.x * 4 + el;

    if (e <= TBL) {
        float tv = (float)e / (float)TBL;
        float w1 = __ldg(W1 + j);
        float u  = fmaf(tv, w1, __ldg(b1 + j));
        float th = tanhf(u);
        s_th[el][j] = th;
        s_dh[el][j] = w1 * (1.f - th * th);
    }
    __syncthreads();

    {
        const int k = tid & 15;
        const int h = (tid >> 4) & 3;
        const int wi = (tid >> 5) & 1;
        float lat = 0.f, dlat = 0.f;
        if (e <= TBL) {
#pragma unroll
            for (int q = 0; q < 16; q++) {
                int jj = h * 16 + q;
                float w2 = __ldg(W2 + jj * 16 + k);
                lat  = fmaf(s_th[el][jj], w2, lat);
                dlat = fmaf(s_dh[el][jj], w2, dlat);
            }
        }
        lat  += __shfl_xor_sync(0xffffffffu, lat,  16);
        dlat += __shfl_xor_sync(0xffffffffu, dlat, 16);
        if (wi == 1 && (tid & 31) < 16) { s_x[el][k] = lat; s_y[el][k] = dlat; }
        __syncthreads();
        if (e <= TBL && wi == 0 && (tid & 31) < 16) {
            g_table[e][2 * k]     = lat + s_x[el][k] + __ldg(b2 + k);
            g_table[e][2 * k + 1] = dlat + s_y[el][k];
        }
    }

    if (blockIdx.x < SUPB) {
        const int ebase = blockIdx.x * 1024 + tid * 4;
        float4 a, t4;
        if (ebase < B_ * P_) {
            a  = __ldg((const float4*)(pp + ebase));
            t4 = __ldg((const float4*)(pt + ebase));
        } else {
            int r = ebase - B_ * P_;
            a  = __ldg((const float4*)(icp + r));
            t4 = __ldg((const float4*)(ict + r));
        }
        float dx = a.x - t4.x, dy = a.y - t4.y, dz = a.z - t4.z, dw = a.w - t4.w;
        float s = fmaf(dx, dx, fmaf(dy, dy, fmaf(dz, dz, dw * dw)));
#pragma unroll
        for (int o = 16; o; o >>= 1) s += __shfl_down_sync(0xffffffffu, s, o);
        if ((tid & 31) == 0) s_red[tid >> 5] = s;
        __syncthreads();
        if (tid == 0) {
            float tot = 0.f;
#pragma unroll
            for (int i = 0; i < 8; i++) tot += s_red[i];
            g_sup[blockIdx.x] = tot;
        }
    }
}

// ---------------------------------------------------------------------------
// Kernel 2: main loss kernel (R4 structure). One block = (batch b, 256 t's).
// Phase A: 8 lanes/t, LDG.128 covers a 128-B table row; PAD-36 staging
// (conflict-free STS.128 and LDS.128 on both sides).
// Phase B: t-parallel, register-lean (in-place observables), physics first.
// ---------------------------------------------------------------------------
__global__ __launch_bounds__(TPB) void main_kernel(
    const float* __restrict__ t_in,
    const float* __restrict__ x_target,
    const float* __restrict__ params) {

    __shared__ float s_t[TPB];
    __shared__ float s_stage[TPB][PAD];
    __shared__ float s_par[P_];
    __shared__ float s_rd[TPB / 32], s_rp[TPB / 32];

    const int tid   = threadIdx.x;
    const int b     = blockIdx.x >> 4;
    const int chunk = blockIdx.x & (CHUNKS - 1);
    const int t0    = chunk * TPB;

    s_t[tid] = __ldg(t_in + (size_t)b * T_ + t0 + tid);
    if (tid < P_) s_par[tid] = __ldg(params + (size_t)b * P_ + tid);
    __syncthreads();

    // ---- Phase A: cooperative vector gather + lerp ----
    const int kk = tid & 7;      // float4 slot (components 2kk, 2kk+1)
    const int ts = tid >> 3;     // base t (0..31)
#pragma unroll
    for (int pass = 0; pass < 8; ++pass) {
        int tcur = ts + pass * 32;
        float tv = s_t[tcur];
        float p  = tv * (float)TBL;
        int   i  = (int)p;
        i = max(0, min(i, TBL - 1));
        float f = p - (float)i;
        const float4* r0 = (const float4*)g_table[i] + kk;
        float4 lo = __ldg(r0);
        float4 hi = __ldg(r0 + 8);       // next row = +32 floats
        float4 res;
        res.x = fmaf(f, hi.x - lo.x, lo.x);
        res.y = fmaf(f, hi.y - lo.y, lo.y);
        res.z = fmaf(f, hi.z - lo.z, lo.z);
        res.w = fmaf(f, hi.w - lo.w, lo.w);
        *(float4*)&s_stage[tcur][kk * 4] = res;
    }
    __syncthreads();

    // ---- Phase B: per-t compute (register-lean) ----
    float lat[16], dlat[16];
#pragma unroll
    for (int jj = 0; jj < 8; jj++) {
        float4 v = *(const float4*)&s_stage[tid][jj * 4];
        lat[2 * jj]      = v.x;
        dlat[2 * jj]     = v.y;
        lat[2 * jj + 1]  = v.z;
        dlat[2 * jj + 1] = v.w;
    }

    // observables in place: lat[8+k] <- relu(q-mu); dlat[8+k] <- jvp
#pragma unroll
    for (int k = 0; k < 8; k++) {
        float s = lat[8 + k] - s_par[8 + k];
        lat[8 + k]  = fmaxf(s, 0.f);
        dlat[8 + k] = (s > 0.f) ? dlat[8 + k] : 0.f;
    }

    // physics loss first (kills dlat before the data-loss loads)
    float acc_p = 0.f;
#pragma unroll
    for (int k = 0; k < 8; k++) {
        float pix = 0.f, ga = 0.f;
#pragma unroll
        for (int j = 0; j < 8; j++) {
            pix = fmaf(s_par[16 + k * 8 + j], lat[8 + j], pix);
            ga  = fmaf(s_par[80 + k * 8 + j], lat[j],     ga);
        }
        float d1 = dlat[k] - (s_par[k] + pix - lat[k]);
        acc_p = fmaf(d1, d1, acc_p);
        float d2 = dlat[8 + k] - ga * (s_par[8 + k] - lat[8 + k]);
        acc_p = fmaf(d2, d2, acc_p);
    }

    // data loss: state == lat[0..15] (coalesced stride-T loads, 16-deep MLP)
    float acc_d = 0.f;
    const float* xt = x_target + (size_t)b * TWO_N * T_ + t0 + tid;
#pragma unroll
    for (int k = 0; k < 16; k++) {
        float d = lat[k] - __ldg(xt + (size_t)k * T_);
        acc_d = fmaf(d, d, acc_d);
    }

    // ---- block reduction ----
#pragma unroll
    for (int o = 16; o; o >>= 1) {
        acc_d += __shfl_down_sync(0xffffffffu, acc_d, o);
        acc_p += __shfl_down_sync(0xffffffffu, acc_p, o);
    }
    const int lane = tid & 31, wid = tid >> 5;
    if (lane == 0) { s_rd[wid] = acc_d; s_rp[wid] = acc_p; }
    __syncthreads();
    if (tid == 0) {
        float sd = 0.f, sp = 0.f;
#pragma unroll
        for (int i = 0; i < TPB / 32; i++) { sd += s_rd[i]; sp += s_rp[i]; }
        g_pd[blockIdx.x] = sd;
        g_pp[blockIdx.x] = sp;
    }
}

// ---------------------------------------------------------------------------
// Kernel 3: finalize — deterministic double sums of tiny partial arrays.
// ---------------------------------------------------------------------------
__global__ void finalize(float* __restrict__ out) {
    const int tid = threadIdx.x;
    double sd = 0.0, sp = 0.0;
    for (int i = tid; i < NBLK; i += 256) {
        sd += (double)g_pd[i];
        sp += (double)g_pp[i];
    }
    double ss = (tid < SUPB) ? (double)g_sup[tid] : 0.0;
    __shared__ double r1[256], r2[256], r3[256];
    r1[tid] = sd; r2[tid] = sp; r3[tid] = ss;
    __syncthreads();
    for (int o = 128; o; o >>= 1) {
        if (tid < o) { r1[tid] += r1[tid + o]; r2[tid] += r2[tid + o]; r3[tid] += r3[tid + o]; }
        __syncthreads();
    }
    if (tid == 0) {
        double res = (r1[0] + r2[0]) / 16777216.0 + r3[0] / 40960.0;
        out[0] = (float)res;
    }
}

// ---------------------------------------------------------------------------
extern "C" void kernel_launch(void* const* d_in, const int* in_sizes, int n_in,
                              void* d_out, int out_size) {
    const float* t   = (const float*)d_in[0];
    const float* xt  = (const float*)d_in[1];
    const float* pp  = (const float*)d_in[2];
    const float* pt  = (const float*)d_in[3];
    const float* icp = (const float*)d_in[4];
    const float* ict = (const float*)d_in[5];
    const float* W1  = (const float*)d_in[6];
    const float* b1  = (const float*)d_in[7];
    const float* W2  = (const float*)d_in[8];
    const float* b2  = (const float*)d_in[9];

    int tbl_blocks = (TBL + 1 + 3) / 4;                 // 33
    int grid1 = tbl_blocks > SUPB ? tbl_blocks : SUPB;  // 40
    build_table<<<grid1, 256>>>(W1, b1, W2, b2, pp, pt, icp, ict);
    main_kernel<<<NBLK, TPB>>>(t, xt, pp);
    finalize<<<1, 256>>>((float*)d_out);
}

// round 9
// speedup vs baseline: 1.2816x; 1.1353x over previous
#include <cuda_runtime.h>
#include <cuda_fp16.h>

#define B_    256
#define T_    4096
#define TWO_N 16
#define H_    64
#define P_    144
#define TBL   128
#define TPB   256
#define TPB1  320
#define CHUNKS (T_/TPB)      // 16
#define NBLK  (B_*CHUNKS)    // 4096
#define SUPB  40             // supervised-loss blocks (40*1024 = 40960 elems)
#define SSTR  20             // stage row stride in words (80 B): conflict-free LDS.128

// fp16 diff table. Row r (128 B): word 2k = half2(lat_k[r], dlat_k[r]),
// word 2k+1 = half2(lat_k[r+1]-lat_k[r], dlat_k[r+1]-dlat_k[r]).
// lerp(t) = hfma2(f2, word(2k+1), word(2k)).  16 KB total -> L1-resident.
__device__ __align__(128) unsigned g_table[TBL][32];
__device__ float g_pd[NBLK];
__device__ float g_pp[NBLK];
__device__ float g_sup[SUPB];

// ---------------------------------------------------------------------------
// Kernel 1: tabulate. Block covers 4 output rows, computing 5 entries
// (overlap window) with 64 threads each. Blocks 0..SUPB-1 fold sup-loss.
// ---------------------------------------------------------------------------
__global__ __launch_bounds__(TPB1) void build_table(
    const float* __restrict__ W1, const float* __restrict__ b1,
    const float* __restrict__ W2, const float* __restrict__ b2,
    const float* __restrict__ pp, const float* __restrict__ pt,
    const float* __restrict__ icp, const float* __restrict__ ict) {

    __shared__ float s_th[5][64];
    __shared__ float s_dh[5][64];
    __shared__ float s_x[5][16], s_y[5][16];
    __shared__ float s_red[8];

    const int tid = threadIdx.x;
    const int el  = tid >> 6;            // 0..4 entry window slot
    const int j   = tid & 63;
    const int e   = blockIdx.x * 4 + el; // table entry index (value grid)
    const bool tb = (blockIdx.x < TBL / 4);   // 32 table blocks

    if (tb && e <= TBL) {
        float tv = (float)e / (float)TBL;
        float w1 = __ldg(W1 + j);
        float u  = fmaf(tv, w1, __ldg(b1 + j));
        float th = tanhf(u);
        s_th[el][j] = th;
        s_dh[el][j] = w1 * (1.f - th * th);
    }
    __syncthreads();

    {
        const int k = tid & 15;
        const int h = (tid >> 4) & 3;
        const int wi = (tid >> 5) & 1;   // warp within entry
        float lat = 0.f, dlat = 0.f;
        if (tb && e <= TBL) {
#pragma unroll
            for (int q = 0; q < 16; q++) {
                int jj = h * 16 + q;
                float w2 = __ldg(W2 + jj * 16 + k);
                lat  = fmaf(s_th[el][jj], w2, lat);
                dlat = fmaf(s_dh[el][jj], w2, dlat);
            }
        }
        lat  += __shfl_xor_sync(0xffffffffu, lat,  16);
        dlat += __shfl_xor_sync(0xffffffffu, dlat, 16);
        if (wi == 1 && (tid & 31) < 16) { s_x[el][k] = lat; s_y[el][k] = dlat; }
        __syncthreads();
        if (tb && e <= TBL && wi == 0 && (tid & 31) < 16) {
            s_x[el][k] = lat + s_x[el][k] + __ldg(b2 + k);   // final lat
            s_y[el][k] = dlat + s_y[el][k];                  // final dlat
        }
    }
    __syncthreads();

    // emit 4 fp16 diff rows per block
    if (tb && tid < 64) {
        const int rr = tid >> 4, k = tid & 15;
        const int r = blockIdx.x * 4 + rr;
        if (r < TBL) {
            float v0 = s_x[rr][k],     d0 = s_y[rr][k];
            float v1 = s_x[rr + 1][k], d1 = s_y[rr + 1][k];
            __half2 hv = __floats2half2_rn(v0, d0);
            __half2 hd = __floats2half2_rn(v1 - v0, d1 - d0);
            uint2 o;
            o.x = *(unsigned*)&hv;
            o.y = *(unsigned*)&hd;
            ((uint2*)g_table[r])[k] = o;
        }
    }

    // supervised loss partials (blocks 0..SUPB-1, first 256 threads)
    if (blockIdx.x < SUPB && tid < 256) {
        const int ebase = blockIdx.x * 1024 + tid * 4;
        float4 a, t4;
        if (ebase < B_ * P_) {
            a  = __ldg((const float4*)(pp + ebase));
            t4 = __ldg((const float4*)(pt + ebase));
        } else {
            int r = ebase - B_ * P_;
            a  = __ldg((const float4*)(icp + r));
            t4 = __ldg((const float4*)(ict + r));
        }
        float dx = a.x - t4.x, dy = a.y - t4.y, dz = a.z - t4.z, dw = a.w - t4.w;
        float s = fmaf(dx, dx, fmaf(dy, dy, fmaf(dz, dz, dw * dw)));
#pragma unroll
        for (int o = 16; o; o >>= 1) s += __shfl_down_sync(0xffffffffu, s, o);
        if ((tid & 31) == 0) s_red[tid >> 5] = s;
        __syncthreads();
        if (tid == 0) {
            float tot = 0.f;
#pragma unroll
            for (int i = 0; i < 8; i++) tot += s_red[i];
            g_sup[blockIdx.x] = tot;
        }
    }
}

// ---------------------------------------------------------------------------
// Kernel 2: main loss. One block = (batch b, 256 t's).
// Phase A: 8 lanes/t, ONE coalesced LDG.128 row read + 2 HFMA2 lerp + STS.64.
// Phase B: t-parallel, fp32 compute; physics first, then streamed data loss.
// ---------------------------------------------------------------------------
__global__ __launch_bounds__(TPB) void main_kernel(
    const float* __restrict__ t_in,
    const float* __restrict__ x_target,
    const float* __restrict__ params) {

    __shared__ float2 s_if[TPB];                       // {row byte-offset, f2 bits}
    __shared__ __align__(16) unsigned s_stage[TPB * SSTR];  // 20 KB, 16 half2/t
    __shared__ float s_par[P_];
    __shared__ float s_rd[TPB / 32], s_rp[TPB / 32];

    const int tid   = threadIdx.x;
    const int b     = blockIdx.x >> 4;
    const int chunk = blockIdx.x & (CHUNKS - 1);
    const int t0    = chunk * TPB;

    // preamble: per-t row offset + fp16 frac
    {
        float tv = __ldg(t_in + (size_t)b * T_ + t0 + tid);
        float p  = tv * (float)TBL;
        int   i  = (int)p;
        i = max(0, min(i, TBL - 1));
        float f = p - (float)i;
        __half2 f2 = __float2half2_rn(f);
        s_if[tid] = make_float2(__int_as_float(i << 7), __uint_as_float(*(unsigned*)&f2));
    }
    if (tid < P_) s_par[tid] = __ldg(params + (size_t)b * P_ + tid);
    __syncthreads();

    // ---- Phase A ----
    const int kk = tid & 7;      // 16-B slot within row (components 2kk, 2kk+1)
    const int ts = tid >> 3;     // base t (0..31)
    const char* tbase = (const char*)g_table + kk * 16;
#pragma unroll
    for (int pass = 0; pass < 8; ++pass) {
        int r = ts + pass * 32;
        float2 v = s_if[r];                       // broadcast within 8-lane group
        uint4 w = __ldg((const uint4*)(tbase + __float_as_int(v.x)));
        unsigned fb = __float_as_uint(v.y);
        __half2 f2 = *(__half2*)&fb;
        __half2 r0 = __hfma2(f2, *(__half2*)&w.y, *(__half2*)&w.x);
        __half2 r1 = __hfma2(f2, *(__half2*)&w.w, *(__half2*)&w.z);
        uint2 st;
        st.x = *(unsigned*)&r0;
        st.y = *(unsigned*)&r1;
        *(uint2*)&s_stage[r * SSTR + kk * 2] = st;
    }
    __syncthreads();

    // ---- Phase B: unpack own t ----
    float lat[16], dlat[16];
#pragma unroll
    for (int c = 0; c < 4; c++) {
        uint4 w = *(const uint4*)&s_stage[tid * SSTR + c * 4];
        unsigned ws0 = w.x, ws1 = w.y, ws2 = w.z, ws3 = w.w;
        float2 v0 = __half22float2(*(__half2*)&ws0);
        float2 v1 = __half22float2(*(__half2*)&ws1);
        float2 v2 = __half22float2(*(__half2*)&ws2);
        float2 v3 = __half22float2(*(__half2*)&ws3);
        lat[c * 4 + 0] = v0.x; dlat[c * 4 + 0] = v0.y;
        lat[c * 4 + 1] = v1.x; dlat[c * 4 + 1] = v1.y;
        lat[c * 4 + 2] = v2.x; dlat[c * 4 + 2] = v2.y;
        lat[c * 4 + 3] = v3.x; dlat[c * 4 + 3] = v3.y;
    }

    // observables in place: lat[8+k] <- relu(q-mu); dlat[8+k] <- jvp
#pragma unroll
    for (int k = 0; k < 8; k++) {
        float s = lat[8 + k] - s_par[8 + k];
        lat[8 + k]  = fmaxf(s, 0.f);
        dlat[8 + k] = (s > 0.f) ? dlat[8 + k] : 0.f;
    }

    // physics loss first
    float acc_p = 0.f;
#pragma unroll
    for (int k = 0; k < 8; k++) {
        float pix = 0.f, ga = 0.f;
#pragma unroll
        for (int j = 0; j < 8; j++) {
            pix = fmaf(s_par[16 + k * 8 + j], lat[8 + j], pix);
            ga  = fmaf(s_par[80 + k * 8 + j], lat[j],     ga);
        }
        float d1 = dlat[k] - (s_par[k] + pix - lat[k]);
        acc_p = fmaf(d1, d1, acc_p);
        float d2 = dlat[8 + k] - ga * (s_par[8 + k] - lat[8 + k]);
        acc_p = fmaf(d2, d2, acc_p);
    }

    // data loss (coalesced stride-T loads)
    float acc_d = 0.f;
    const float* xt = x_target + (size_t)b * TWO_N * T_ + t0 + tid;
#pragma unroll
    for (int k = 0; k < 16; k++) {
        float d = lat[k] - __ldg(xt + (size_t)k * T_);
        acc_d = fmaf(d, d, acc_d);
    }

    // ---- block reduction ----
#pragma unroll
    for (int o = 16; o; o >>= 1) {
        acc_d += __shfl_down_sync(0xffffffffu, acc_d, o);
        acc_p += __shfl_down_sync(0xffffffffu, acc_p, o);
    }
    const int lane = tid & 31, wid = tid >> 5;
    if (lane == 0) { s_rd[wid] = acc_d; s_rp[wid] = acc_p; }
    __syncthreads();
    if (tid == 0) {
        float sd = 0.f, sp = 0.f;
#pragma unroll
        for (int i = 0; i < TPB / 32; i++) { sd += s_rd[i]; sp += s_rp[i]; }
        g_pd[blockIdx.x] = sd;
        g_pp[blockIdx.x] = sp;
    }
}

// ---------------------------------------------------------------------------
// Kernel 3: finalize — deterministic double sums of tiny partial arrays.
// ---------------------------------------------------------------------------
__global__ void finalize(float* __restrict__ out) {
    const int tid = threadIdx.x;
    double sd = 0.0, sp = 0.0;
    for (int i = tid; i < NBLK; i += 256) {
        sd += (double)g_pd[i];
        sp += (double)g_pp[i];
    }
    double ss = (tid < SUPB) ? (double)g_sup[tid] : 0.0;
    __shared__ double r1[256], r2[256], r3[256];
    r1[tid] = sd; r2[tid] = sp; r3[tid] = ss;
    __syncthreads();
    for (int o = 128; o; o >>= 1) {
        if (tid < o) { r1[tid] += r1[tid + o]; r2[tid] += r2[tid + o]; r3[tid] += r3[tid + o]; }
        __syncthreads();
    }
    if (tid == 0) {
        double res = (r1[0] + r2[0]) / 16777216.0 + r3[0] / 40960.0;
        out[0] = (float)res;
    }
}

// ---------------------------------------------------------------------------
extern "C" void kernel_launch(void* const* d_in, const int* in_sizes, int n_in,
                              void* d_out, int out_size) {
    const float* t   = (const float*)d_in[0];
    const float* xt  = (const float*)d_in[1];
    const float* pp  = (const float*)d_in[2];
    const float* pt  = (const float*)d_in[3];
    const float* icp = (const float*)d_in[4];
    const float* ict = (const float*)d_in[5];
    const float* W1  = (const float*)d_in[6];
    const float* b1  = (const float*)d_in[7];
    const float* W2  = (const float*)d_in[8];
    const float* b2  = (const float*)d_in[9];

    build_table<<<SUPB, TPB1>>>(W1, b1, W2, b2, pp, pt, icp, ict);  // 40 >= 32 table blocks
    main_kernel<<<NBLK, TPB>>>(t, xt, pp);
    finalize<<<1, 256>>>((float*)d_out);
}

// round 11
// speedup vs baseline: 1.4221x; 1.1096x over previous
#include <cuda_runtime.h>
#include <cuda_fp16.h>

#define B_    256
#define T_    4096
#define TWO_N 16
#define H_    64
#define P_    144
#define TBL   128
#define TPB   256
#define TPB1  320
#define TPERB 512            // t's per block (2 per thread)
#define NBLK  (B_*T_/TPERB)  // 2048
#define SUPB  40             // supervised-loss blocks (40*1024 = 40960 elems)
#define SSTR  36             // words per PAIR of stage rows (144 B, 16B-aligned)

// fp16 diff table. Row r (128 B): word 2k = half2(lat_k[r], dlat_k[r]),
// word 2k+1 = half2(lat_k[r+1]-lat_k[r], dlat_k[r+1]-dlat_k[r]).
// lerp(t) = hfma2(f2, word(2k+1), word(2k)).  16 KB total -> L1-resident.
__device__ __align__(128) unsigned g_table[TBL][32];
__device__ float g_pd[NBLK];
__device__ float g_pp[NBLK];
__device__ float g_sup[SUPB];

// ---------------------------------------------------------------------------
// Kernel 1: tabulate. Block covers 4 output rows, computing 5 entries
// (overlap window) with 64 threads each. Blocks 0..SUPB-1 fold sup-loss.
// ---------------------------------------------------------------------------
__global__ __launch_bounds__(TPB1) void build_table(
    const float* __restrict__ W1, const float* __restrict__ b1,
    const float* __restrict__ W2, const float* __restrict__ b2,
    const float* __restrict__ pp, const float* __restrict__ pt,
    const float* __restrict__ icp, const float* __restrict__ ict) {

    __shared__ float s_th[5][64];
    __shared__ float s_dh[5][64];
    __shared__ float s_x[5][16], s_y[5][16];
    __shared__ float s_red[8];

    const int tid = threadIdx.x;
    const int el  = tid >> 6;            // 0..4 entry window slot
    const int j   = tid & 63;
    const int e   = blockIdx.x * 4 + el; // table entry index (value grid)
    const bool tb = (blockIdx.x < TBL / 4);   // 32 table blocks

    if (tb && e <= TBL) {
        float tv = (float)e / (float)TBL;
        float w1 = __ldg(W1 + j);
        float u  = fmaf(tv, w1, __ldg(b1 + j));
        float th = tanhf(u);
        s_th[el][j] = th;
        s_dh[el][j] = w1 * (1.f - th * th);
    }
    __syncthreads();

    {
        const int k = tid & 15;
        const int h = (tid >> 4) & 3;
        const int wi = (tid >> 5) & 1;   // warp within entry
        float lat = 0.f, dlat = 0.f;
        if (tb && e <= TBL) {
#pragma unroll
            for (int q = 0; q < 16; q++) {
                int jj = h * 16 + q;
                float w2 = __ldg(W2 + jj * 16 + k);
                lat  = fmaf(s_th[el][jj], w2, lat);
                dlat = fmaf(s_dh[el][jj], w2, dlat);
            }
        }
        lat  += __shfl_xor_sync(0xffffffffu, lat,  16);
        dlat += __shfl_xor_sync(0xffffffffu, dlat, 16);
        if (wi == 1 && (tid & 31) < 16) { s_x[el][k] = lat; s_y[el][k] = dlat; }
        __syncthreads();
        if (tb && e <= TBL && wi == 0 && (tid & 31) < 16) {
            s_x[el][k] = lat + s_x[el][k] + __ldg(b2 + k);   // final lat
            s_y[el][k] = dlat + s_y[el][k];                  // final dlat
        }
    }
    __syncthreads();

    // emit 4 fp16 diff rows per block
    if (tb && tid < 64) {
        const int rr = tid >> 4, k = tid & 15;
        const int r = blockIdx.x * 4 + rr;
        if (r < TBL) {
            float v0 = s_x[rr][k],     d0 = s_y[rr][k];
            float v1 = s_x[rr + 1][k], d1 = s_y[rr + 1][k];
            __half2 hv = __floats2half2_rn(v0, d0);
            __half2 hd = __floats2half2_rn(v1 - v0, d1 - d0);
            uint2 o;
            o.x = *(unsigned*)&hv;
            o.y = *(unsigned*)&hd;
            ((uint2*)g_table[r])[k] = o;
        }
    }

    // supervised loss partials (blocks 0..SUPB-1, first 256 threads)
    if (blockIdx.x < SUPB && tid < 256) {
        const int ebase = blockIdx.x * 1024 + tid * 4;
        float4 a, t4;
        if (ebase < B_ * P_) {
            a  = __ldg((const float4*)(pp + ebase));
            t4 = __ldg((const float4*)(pt + ebase));
        } else {
            int r = ebase - B_ * P_;
            a  = __ldg((const float4*)(icp + r));
            t4 = __ldg((const float4*)(ict + r));
        }
        float dx = a.x - t4.x, dy = a.y - t4.y, dz = a.z - t4.z, dw = a.w - t4.w;
        float s = fmaf(dx, dx, fmaf(dy, dy, fmaf(dz, dz, dw * dw)));
#pragma unroll
        for (int o = 16; o; o >>= 1) s += __shfl_down_sync(0xffffffffu, s, o);
        if ((tid & 31) == 0) s_red[tid >> 5] = s;
        __syncthreads();
        if (tid == 0) {
            float tot = 0.f;
#pragma unroll
            for (int i = 0; i < 8; i++) tot += s_red[i];
            g_sup[blockIdx.x] = tot;
        }
    }
}

// ---------------------------------------------------------------------------
// Kernel 2: main loss. One block = (batch b, 512 t's); 2 consecutive t's per
// thread. Phase A: 8 lanes/t, one LDG.128 + 2 HFMA2 + STS.64 per row.
// Stage: pair layout, stride 36 words -> conflict-free STS.64 and LDS.128.
// Phase B: per-pair compute; data loss uses float2 loads (2 t's per LDG.64).
// ---------------------------------------------------------------------------
__global__ __launch_bounds__(TPB) void main_kernel(
    const float* __restrict__ t_in,
    const float* __restrict__ x_target,
    const float* __restrict__ params) {

    __shared__ float2 s_if[TPERB];                    // {row byte-offset, f2 bits}
    __shared__ __align__(16) unsigned s_stage[TPB * SSTR];  // 36 KB
    __shared__ float s_par[P_];
    __shared__ float s_rd[TPB / 32], s_rp[TPB / 32];

    const int tid  = threadIdx.x;
    const int b    = blockIdx.x >> 3;
    const int half = blockIdx.x & 7;
    const int t0   = half * TPERB;

    // preamble: per-t row offset + fp16 frac (2 t's per thread, coalesced)
#pragma unroll
    for (int q = 0; q < 2; q++) {
        int lt = tid + q * TPB;
        float tv = __ldg(t_in + (size_t)b * T_ + t0 + lt);
        float p  = tv * (float)TBL;
        int   i  = (int)p;
        i = max(0, min(i, TBL - 1));
        float f = p - (float)i;
        __half2 f2 = __float2half2_rn(f);
        s_if[lt] = make_float2(__int_as_float(i << 7), __uint_as_float(*(unsigned*)&f2));
    }
    if (tid < P_) s_par[tid] = __ldg(params + (size_t)b * P_ + tid);
    __syncthreads();

    // ---- Phase A: 16 passes cover 512 rows ----
    const int kk = tid & 7;      // 16-B slot within row
    const int ts = tid >> 3;     // base row (0..31)
    const char* tbase = (const char*)g_table + kk * 16;
#pragma unroll
    for (int pass = 0; pass < 16; ++pass) {
        int r = ts + pass * 32;
        float2 v = s_if[r];
        uint4 w = __ldg((const uint4*)(tbase + __float_as_int(v.x)));
        unsigned fb = __float_as_uint(v.y);
        __half2 f2 = *(__half2*)&fb;
        __half2 r0 = __hfma2(f2, *(__half2*)&w.y, *(__half2*)&w.x);
        __half2 r1 = __hfma2(f2, *(__half2*)&w.w, *(__half2*)&w.z);
        uint2 st;
        st.x = *(unsigned*)&r0;
        st.y = *(unsigned*)&r1;
        // pair layout: row r at (r>>1)*SSTR + (r&1)*16 + kk*2
        *(uint2*)&s_stage[(r >> 1) * SSTR + (r & 1) * 16 + kk * 2] = st;
    }
    __syncthreads();

    float acc_p = 0.f;
    float latA[16], latB[16];

    // ---- Phase B, t-even: unpack, observables, physics ----
    {
        float dlat[16];
#pragma unroll
        for (int c = 0; c < 4; c++) {
            uint4 w = *(const uint4*)&s_stage[tid * SSTR + c * 4];
            unsigned w0 = w.x, w1 = w.y, w2 = w.z, w3 = w.w;
            float2 v0 = __half22float2(*(__half2*)&w0);
            float2 v1 = __half22float2(*(__half2*)&w1);
            float2 v2 = __half22float2(*(__half2*)&w2);
            float2 v3 = __half22float2(*(__half2*)&w3);
            latA[c * 4 + 0] = v0.x; dlat[c * 4 + 0] = v0.y;
            latA[c * 4 + 1] = v1.x; dlat[c * 4 + 1] = v1.y;
            latA[c * 4 + 2] = v2.x; dlat[c * 4 + 2] = v2.y;
            latA[c * 4 + 3] = v3.x; dlat[c * 4 + 3] = v3.y;
        }
#pragma unroll
        for (int k = 0; k < 8; k++) {
            float s = latA[8 + k] - s_par[8 + k];
            latA[8 + k] = fmaxf(s, 0.f);
            dlat[8 + k] = (s > 0.f) ? dlat[8 + k] : 0.f;
        }
#pragma unroll
        for (int k = 0; k < 8; k++) {
            float pix = 0.f, ga = 0.f;
#pragma unroll
            for (int j = 0; j < 8; j++) {
                pix = fmaf(s_par[16 + k * 8 + j], latA[8 + j], pix);
                ga  = fmaf(s_par[80 + k * 8 + j], latA[j],     ga);
            }
            float d1 = dlat[k] - (s_par[k] + pix - latA[k]);
            acc_p = fmaf(d1, d1, acc_p);
            float d2 = dlat[8 + k] - ga * (s_par[8 + k] - latA[8 + k]);
            acc_p = fmaf(d2, d2, acc_p);
        }
    }

    // ---- Phase B, t-odd ----
    {
        float dlat[16];
#pragma unroll
        for (int c = 0; c < 4; c++) {
            uint4 w = *(const uint4*)&s_stage[tid * SSTR + 16 + c * 4];
            unsigned w0 = w.x, w1 = w.y, w2 = w.z, w3 = w.w;
            float2 v0 = __half22float2(*(__half2*)&w0);
            float2 v1 = __half22float2(*(__half2*)&w1);
            float2 v2 = __half22float2(*(__half2*)&w2);
            float2 v3 = __half22float2(*(__half2*)&w3);
            latB[c * 4 + 0] = v0.x; dlat[c * 4 + 0] = v0.y;
            latB[c * 4 + 1] = v1.x; dlat[c * 4 + 1] = v1.y;
            latB[c * 4 + 2] = v2.x; dlat[c * 4 + 2] = v2.y;
            latB[c * 4 + 3] = v3.x; dlat[c * 4 + 3] = v3.y;
        }
#pragma unroll
        for (int k = 0; k < 8; k++) {
            float s = latB[8 + k] - s_par[8 + k];
            latB[8 + k] = fmaxf(s, 0.f);
            dlat[8 + k] = (s > 0.f) ? dlat[8 + k] : 0.f;
        }
#pragma unroll
        for (int k = 0; k < 8; k++) {
            float pix = 0.f, ga = 0.f;
#pragma unroll
            for (int j = 0; j < 8; j++) {
                pix = fmaf(s_par[16 + k * 8 + j], latB[8 + j], pix);
                ga  = fmaf(s_par[80 + k * 8 + j], latB[j],     ga);
            }
            float d1 = dlat[k] - (s_par[k] + pix - latB[k]);
            acc_p = fmaf(d1, d1, acc_p);
            float d2 = dlat[8 + k] - ga * (s_par[8 + k] - latB[8 + k]);
            acc_p = fmaf(d2, d2, acc_p);
        }
    }

    // ---- data loss: float2 loads cover both t's ----
    float acc_d = 0.f;
    const float* xt = x_target + (size_t)b * TWO_N * T_ + t0 + 2 * tid;
#pragma unroll
    for (int k = 0; k < 16; k++) {
        float2 v = __ldg((const float2*)(xt + (size_t)k * T_));
        float d0 = latA[k] - v.x;
        float d1 = latB[k] - v.y;
        acc_d = fmaf(d0, d0, fmaf(d1, d1, acc_d));
    }

    // ---- block reduction ----
#pragma unroll
    for (int o = 16; o; o >>= 1) {
        acc_d += __shfl_down_sync(0xffffffffu, acc_d, o);
        acc_p += __shfl_down_sync(0xffffffffu, acc_p, o);
    }
    const int lane = tid & 31, wid = tid >> 5;
    if (lane == 0) { s_rd[wid] = acc_d; s_rp[wid] = acc_p; }
    __syncthreads();
    if (tid == 0) {
        float sd = 0.f, sp = 0.f;
#pragma unroll
        for (int i = 0; i < TPB / 32; i++) { sd += s_rd[i]; sp += s_rp[i]; }
        g_pd[blockIdx.x] = sd;
        g_pp[blockIdx.x] = sp;
    }
}

// ---------------------------------------------------------------------------
// Kernel 3: finalize — deterministic double sums of tiny partial arrays.
// ---------------------------------------------------------------------------
__global__ void finalize(float* __restrict__ out) {
    const int tid = threadIdx.x;
    double sd = 0.0, sp = 0.0;
    for (int i = tid; i < NBLK; i += 256) {
        sd += (double)g_pd[i];
        sp += (double)g_pp[i];
    }
    double ss = (tid < SUPB) ? (double)g_sup[tid] : 0.0;
    __shared__ double r1[256], r2[256], r3[256];
    r1[tid] = sd; r2[tid] = sp; r3[tid] = ss;
    __syncthreads();
    for (int o = 128; o; o >>= 1) {
        if (tid < o) { r1[tid] += r1[tid + o]; r2[tid] += r2[tid + o]; r3[tid] += r3[tid + o]; }
        __syncthreads();
    }
    if (tid == 0) {
        double res = (r1[0] + r2[0]) / 16777216.0 + r3[0] / 40960.0;
        out[0] = (float)res;
    }
}

// ---------------------------------------------------------------------------
extern "C" void kernel_launch(void* const* d_in, const int* in_sizes, int n_in,
                              void* d_out, int out_size) {
    const float* t   = (const float*)d_in[0];
    const float* xt  = (const float*)d_in[1];
    const float* pp  = (const float*)d_in[2];
    const float* pt  = (const float*)d_in[3];
    const float* icp = (const float*)d_in[4];
    const float* ict = (const float*)d_in[5];
    const float* W1  = (const float*)d_in[6];
    const float* b1  = (const float*)d_in[7];
    const float* W2  = (const float*)d_in[8];
    const float* b2  = (const float*)d_in[9];

    build_table<<<SUPB, TPB1>>>(W1, b1, W2, b2, pp, pt, icp, ict);
    main_kernel<<<NBLK, TPB>>>(t, xt, pp);
    finalize<<<1, 256>>>((float*)d_out);
}

// round 12
// speedup vs baseline: 1.4232x; 1.0008x over previous
#include <cuda_runtime.h>
#include <cuda_fp16.h>

#define B_    256
#define T_    4096
#define TWO_N 16
#define H_    64
#define P_    144
#define TBL   128
#define TPB   256
#define TPB1  320
#define TPERB 512            // t's per block (2 per thread)
#define NBLK  (B_*T_/TPERB)  // 2048
#define SUPB  40             // supervised-loss blocks (40*1024 = 40960 elems)
#define SSTR  36             // words per PAIR of stage rows (144 B, 16B-aligned)

typedef unsigned long long ull;

// packed f32x2 helpers (Blackwell FFMA2 path — PTX only)
__device__ __forceinline__ ull pk2(float lo, float hi) {
    ull r; asm("mov.b64 %0,{%1,%2};" : "=l"(r) : "f"(lo), "f"(hi)); return r;
}
__device__ __forceinline__ float2 upk2(ull a) {
    float2 r; asm("mov.b64 {%0,%1},%2;" : "=f"(r.x), "=f"(r.y) : "l"(a)); return r;
}
__device__ __forceinline__ ull fma2(ull a, ull b, ull c) {
    ull d; asm("fma.rn.f32x2 %0,%1,%2,%3;" : "=l"(d) : "l"(a), "l"(b), "l"(c)); return d;
}
#define MINUS1_2 0xBF800000BF800000ull   // packed (-1.0f, -1.0f)

// fp16 diff table. Row r (128 B): word 2k = half2(lat_k[r], dlat_k[r]),
// word 2k+1 = half2(delta lat_k, delta dlat_k).  16 KB -> L1-resident.
__device__ __align__(128) unsigned g_table[TBL][32];
__device__ float g_pd[NBLK];
__device__ float g_pp[NBLK];
__device__ float g_sup[SUPB];

// ---------------------------------------------------------------------------
// Kernel 1: tabulate (unchanged from R11). Blocks 0..SUPB-1 fold sup-loss.
// ---------------------------------------------------------------------------
__global__ __launch_bounds__(TPB1) void build_table(
    const float* __restrict__ W1, const float* __restrict__ b1,
    const float* __restrict__ W2, const float* __restrict__ b2,
    const float* __restrict__ pp, const float* __restrict__ pt,
    const float* __restrict__ icp, const float* __restrict__ ict) {

    __shared__ float s_th[5][64];
    __shared__ float s_dh[5][64];
    __shared__ float s_x[5][16], s_y[5][16];
    __shared__ float s_red[8];

    const int tid = threadIdx.x;
    const int el  = tid >> 6;
    const int j   = tid & 63;
    const int e   = blockIdx.x * 4 + el;
    const bool tb = (blockIdx.x < TBL / 4);

    if (tb && e <= TBL) {
        float tv = (float)e / (float)TBL;
        float w1 = __ldg(W1 + j);
        float u  = fmaf(tv, w1, __ldg(b1 + j));
        float th = tanhf(u);
        s_th[el][j] = th;
        s_dh[el][j] = w1 * (1.f - th * th);
    }
    __syncthreads();

    {
        const int k = tid & 15;
        const int h = (tid >> 4) & 3;
        const int wi = (tid >> 5) & 1;
        float lat = 0.f, dlat = 0.f;
        if (tb && e <= TBL) {
#pragma unroll
            for (int q = 0; q < 16; q++) {
                int jj = h * 16 + q;
                float w2 = __ldg(W2 + jj * 16 + k);
                lat  = fmaf(s_th[el][jj], w2, lat);
                dlat = fmaf(s_dh[el][jj], w2, dlat);
            }
        }
        lat  += __shfl_xor_sync(0xffffffffu, lat,  16);
        dlat += __shfl_xor_sync(0xffffffffu, dlat, 16);
        if (wi == 1 && (tid & 31) < 16) { s_x[el][k] = lat; s_y[el][k] = dlat; }
        __syncthreads();
        if (tb && e <= TBL && wi == 0 && (tid & 31) < 16) {
            s_x[el][k] = lat + s_x[el][k] + __ldg(b2 + k);
            s_y[el][k] = dlat + s_y[el][k];
        }
    }
    __syncthreads();

    if (tb && tid < 64) {
        const int rr = tid >> 4, k = tid & 15;
        const int r = blockIdx.x * 4 + rr;
        if (r < TBL) {
            float v0 = s_x[rr][k],     d0 = s_y[rr][k];
            float v1 = s_x[rr + 1][k], d1 = s_y[rr + 1][k];
            __half2 hv = __floats2half2_rn(v0, d0);
            __half2 hd = __floats2half2_rn(v1 - v0, d1 - d0);
            uint2 o;
            o.x = *(unsigned*)&hv;
            o.y = *(unsigned*)&hd;
            ((uint2*)g_table[r])[k] = o;
        }
    }

    if (blockIdx.x < SUPB && tid < 256) {
        const int ebase = blockIdx.x * 1024 + tid * 4;
        float4 a, t4;
        if (ebase < B_ * P_) {
            a  = __ldg((const float4*)(pp + ebase));
            t4 = __ldg((const float4*)(pt + ebase));
        } else {
            int r = ebase - B_ * P_;
            a  = __ldg((const float4*)(icp + r));
            t4 = __ldg((const float4*)(ict + r));
        }
        float dx = a.x - t4.x, dy = a.y - t4.y, dz = a.z - t4.z, dw = a.w - t4.w;
        float s = fmaf(dx, dx, fmaf(dy, dy, fmaf(dz, dz, dw * dw)));
#pragma unroll
        for (int o = 16; o; o >>= 1) s += __shfl_down_sync(0xffffffffu, s, o);
        if ((tid & 31) == 0) s_red[tid >> 5] = s;
        __syncthreads();
        if (tid == 0) {
            float tot = 0.f;
#pragma unroll
            for (int i = 0; i < 8; i++) tot += s_red[i];
            g_sup[blockIdx.x] = tot;
        }
    }
}

// ---------------------------------------------------------------------------
// Kernel 2: main loss. One block = (batch b, 512 t's); 2 consecutive t's per
// thread, Phase B fully packed f32x2 (one FFMA2 serves both t's).
// ---------------------------------------------------------------------------
__global__ __launch_bounds__(TPB) void main_kernel(
    const float* __restrict__ t_in,
    const float* __restrict__ x_target,
    const float* __restrict__ params) {

    __shared__ float2 s_if[TPERB];                    // {row byte-offset, f2 bits}
    __shared__ __align__(16) unsigned s_stage[TPB * SSTR];  // 36 KB
    __shared__ float s_par[P_];
    __shared__ ull   s_par2[P_];                      // broadcast-packed params
    __shared__ float s_rd[TPB / 32], s_rp[TPB / 32];

    const int tid  = threadIdx.x;
    const int b    = blockIdx.x >> 3;
    const int half = blockIdx.x & 7;
    const int t0   = half * TPERB;

    // preamble
#pragma unroll
    for (int q = 0; q < 2; q++) {
        int lt = tid + q * TPB;
        float tv = __ldg(t_in + (size_t)b * T_ + t0 + lt);
        float p  = tv * (float)TBL;
        int   i  = (int)p;
        i = max(0, min(i, TBL - 1));
        float f = p - (float)i;
        __half2 f2 = __float2half2_rn(f);
        s_if[lt] = make_float2(__int_as_float(i << 7), __uint_as_float(*(unsigned*)&f2));
    }
    if (tid < P_) {
        float v = __ldg(params + (size_t)b * P_ + tid);
        s_par[tid]  = v;
        s_par2[tid] = pk2(v, v);
    }
    __syncthreads();

    // ---- Phase A: 16 passes cover 512 rows ----
    const int kk = tid & 7;
    const int ts = tid >> 3;
    const char* tbase = (const char*)g_table + kk * 16;
#pragma unroll
    for (int pass = 0; pass < 16; ++pass) {
        int r = ts + pass * 32;
        float2 v = s_if[r];
        uint4 w = __ldg((const uint4*)(tbase + __float_as_int(v.x)));
        unsigned fb = __float_as_uint(v.y);
        __half2 f2 = *(__half2*)&fb;
        __half2 r0 = __hfma2(f2, *(__half2*)&w.y, *(__half2*)&w.x);
        __half2 r1 = __hfma2(f2, *(__half2*)&w.w, *(__half2*)&w.z);
        uint2 st;
        st.x = *(unsigned*)&r0;
        st.y = *(unsigned*)&r1;
        *(uint2*)&s_stage[(r >> 1) * SSTR + (r & 1) * 16 + kk * 2] = st;
    }
    __syncthreads();

    // ---- Phase B: unpack both t's, pack across-t f32x2 ----
    ull lat2[16];   // component c packed (t_even, t_odd); c>=8 holds x=relu(q-mu)
    ull e2[8];      // lat_c + dlat_c   (c = 0..7)
    ull nj2[8];     // -relu'(q-mu)*dlat_{8+c}
    {
        unsigned we[16], wo[16];
#pragma unroll
        for (int c = 0; c < 4; c++) {
            uint4 a = *(const uint4*)&s_stage[tid * SSTR + c * 4];
            we[c * 4 + 0] = a.x; we[c * 4 + 1] = a.y; we[c * 4 + 2] = a.z; we[c * 4 + 3] = a.w;
            uint4 o = *(const uint4*)&s_stage[tid * SSTR + 16 + c * 4];
            wo[c * 4 + 0] = o.x; wo[c * 4 + 1] = o.y; wo[c * 4 + 2] = o.z; wo[c * 4 + 3] = o.w;
        }
#pragma unroll
        for (int c = 0; c < 8; c++) {
            float2 A = __half22float2(*(__half2*)&we[c]);
            float2 Bv = __half22float2(*(__half2*)&wo[c]);
            lat2[c] = pk2(A.x, Bv.x);
            e2[c]   = pk2(A.x + A.y, Bv.x + Bv.y);
        }
#pragma unroll
        for (int c = 8; c < 16; c++) {
            float2 A = __half22float2(*(__half2*)&we[c]);
            float2 Bv = __half22float2(*(__half2*)&wo[c]);
            float muv = s_par[c];            // mu_k at s_par[8+k], k=c-8
            float sA = A.x - muv, sB = Bv.x - muv;
            lat2[c] = pk2(fmaxf(sA, 0.f), fmaxf(sB, 0.f));
            float jA = (sA > 0.f) ? A.y : 0.f;
            float jB = (sB > 0.f) ? Bv.y : 0.f;
            nj2[c - 8] = pk2(-jA, -jB);
        }
    }

    // ---- physics loss, packed ----
    ull accp = 0ull;
#pragma unroll
    for (int k = 0; k < 8; k++) {
        // d1 = e - g - Pi@x  (negated residual; square identical)
        ull pix = fma2(e2[k], MINUS1_2, s_par2[k]);          // g - e
#pragma unroll
        for (int j = 0; j < 8; j++)
            pix = fma2(s_par2[16 + k * 8 + j], lat2[8 + j], pix);
        accp = fma2(pix, pix, accp);
        // d2 = ga*(mu-x) - jvp  (negated; square identical)
        ull m2 = fma2(lat2[8 + k], MINUS1_2, s_par2[8 + k]); // mu - x
        ull ga = 0ull;
#pragma unroll
        for (int j = 0; j < 8; j++)
            ga = fma2(s_par2[80 + k * 8 + j], lat2[j], ga);
        ull dd = fma2(ga, m2, nj2[k]);
        accp = fma2(dd, dd, accp);
    }

    // ---- data loss, packed (u64 stream loads cover both t's) ----
    ull accd = 0ull;
    const ull* xt = (const ull*)(x_target + (size_t)b * TWO_N * T_ + t0 + 2 * tid);
#pragma unroll
    for (int k = 0; k < 16; k++) {
        ull v = __ldg(xt + (size_t)k * (T_ / 2));
        ull d = fma2(v, MINUS1_2, lat2[k]);
        accd = fma2(d, d, accd);
    }

    // ---- block reduction ----
    float2 ap = upk2(accp), ad = upk2(accd);
    float acc_p = ap.x + ap.y;
    float acc_d = ad.x + ad.y;
#pragma unroll
    for (int o = 16; o; o >>= 1) {
        acc_d += __shfl_down_sync(0xffffffffu, acc_d, o);
        acc_p += __shfl_down_sync(0xffffffffu, acc_p, o);
    }
    const int lane = tid & 31, wid = tid >> 5;
    if (lane == 0) { s_rd[wid] = acc_d; s_rp[wid] = acc_p; }
    __syncthreads();
    if (tid == 0) {
        float sd = 0.f, sp = 0.f;
#pragma unroll
        for (int i = 0; i < TPB / 32; i++) { sd += s_rd[i]; sp += s_rp[i]; }
        g_pd[blockIdx.x] = sd;
        g_pp[blockIdx.x] = sp;
    }
}

// ---------------------------------------------------------------------------
// Kernel 3: finalize — deterministic double sums of tiny partial arrays.
// ---------------------------------------------------------------------------
__global__ void finalize(float* __restrict__ out) {
    const int tid = threadIdx.x;
    double sd = 0.0, sp = 0.0;
    for (int i = tid; i < NBLK; i += 256) {
        sd += (double)g_pd[i];
        sp += (double)g_pp[i];
    }
    double ss = (tid < SUPB) ? (double)g_sup[tid] : 0.0;
    __shared__ double r1[256], r2[256], r3[256];
    r1[tid] = sd; r2[tid] = sp; r3[tid] = ss;
    __syncthreads();
    for (int o = 128; o; o >>= 1) {
        if (tid < o) { r1[tid] += r1[tid + o]; r2[tid] += r2[tid + o]; r3[tid] += r3[tid + o]; }
        __syncthreads();
    }
    if (tid == 0) {
        double res = (r1[0] + r2[0]) / 16777216.0 + r3[0] / 40960.0;
        out[0] = (float)res;
    }
}

// ---------------------------------------------------------------------------
extern "C" void kernel_launch(void* const* d_in, const int* in_sizes, int n_in,
                              void* d_out, int out_size) {
    const float* t   = (const float*)d_in[0];
    const float* xt  = (const float*)d_in[1];
    const float* pp  = (const float*)d_in[2];
    const float* pt  = (const float*)d_in[3];
    const float* icp = (const float*)d_in[4];
    const float* ict = (const float*)d_in[5];
    const float* W1  = (const float*)d_in[6];
    const float* b1  = (const float*)d_in[7];
    const float* W2  = (const float*)d_in[8];
    const float* b2  = (const float*)d_in[9];

    build_table<<<SUPB, TPB1>>>(W1, b1, W2, b2, pp, pt, icp, ict);
    main_kernel<<<NBLK, TPB>>>(t, xt, pp);
    finalize<<<1, 256>>>((float*)d_out);
}